// round 14
// baseline (speedup 1.0000x reference)
#include <cuda_runtime.h>
#include <cstdint>
#include <math.h>

// Problem constants
#define Bb  2
#define Tt  2048
#define Dd  2048
#define Hh  16
#define DHd 128
#define MR  4096      // Bb*Tt rows

// ---------------- scratch (static device globals; no allocation) ----------------
// QKV stacked: Q at 0, K at +MR*Dd, V at +2*MR*Dd
__device__ float g_QKV[(size_t)3 * MR * Dd];
__device__ float g_AO [(size_t)MR * Dd];        // 16-perm + tf32-rounded attention out
__device__ float g_Xr [(size_t)MR * Dd];        // tf32-rounded + 16-perm X
__device__ float g_Wr [(size_t)3 * Dd * Dd];    // tf32-rounded + 16-perm weights (stacked)
__device__ float g_cosT[Tt * (DHd / 2)];
__device__ float g_sinT[Tt * (DHd / 2)];

// ---------------- helpers ----------------
__device__ __forceinline__ uint32_t f2tf(float x) {
    uint32_t r;
    asm("cvt.rna.tf32.f32 %0, %1;" : "=r"(r) : "f"(x));
    return r;
}
__device__ __forceinline__ float rtf(float x) { return __uint_as_float(f2tf(x)); }

__device__ __forceinline__ void mma8(float c[4], const uint32_t a[4], uint32_t b0, uint32_t b1) {
    asm volatile(
        "mma.sync.aligned.m16n8k8.row.col.f32.tf32.tf32.f32 "
        "{%0,%1,%2,%3}, {%4,%5,%6,%7}, {%8,%9}, {%0,%1,%2,%3};\n"
        : "+f"(c[0]), "+f"(c[1]), "+f"(c[2]), "+f"(c[3])
        : "r"(a[0]), "r"(a[1]), "r"(a[2]), "r"(a[3]), "r"(b0), "r"(b1));
}

// scalar-operand variant (avoids array reg shuffles when feeding uint4 lanes)
__device__ __forceinline__ void mma8s(float c[4], uint32_t a0, uint32_t a1,
                                      uint32_t a2, uint32_t a3,
                                      uint32_t b0, uint32_t b1) {
    asm volatile(
        "mma.sync.aligned.m16n8k8.row.col.f32.tf32.tf32.f32 "
        "{%0,%1,%2,%3}, {%4,%5,%6,%7}, {%8,%9}, {%0,%1,%2,%3};\n"
        : "+f"(c[0]), "+f"(c[1]), "+f"(c[2]), "+f"(c[3])
        : "r"(a0), "r"(a1), "r"(a2), "r"(a3), "r"(b0), "r"(b1));
}

__device__ __forceinline__ void cp16(float* s, const float* g) {
    uint32_t sa = (uint32_t)__cvta_generic_to_shared(s);
    asm volatile("cp.async.cg.shared.global [%0], [%1], 16;\n" :: "r"(sa), "l"(g));
}
__device__ __forceinline__ void cp_commit() { asm volatile("cp.async.commit_group;\n"); }
template <int N>
__device__ __forceinline__ void cp_wait() { asm volatile("cp.async.wait_group %0;\n" :: "n"(N)); }

// ---------------- tf32 round + 16-group k-permute: out[4q+j] = in[q+4j] -------
// (4x4 transpose per 16 floats) -> one LDS.128 at chunk qc yields k = qc,qc+4,qc+8,qc+12.
__global__ void round_perm_tf32(const float* __restrict__ in, float* __restrict__ out, int n16) {
    int g = blockIdx.x * blockDim.x + threadIdx.x;
    if (g >= n16) return;
    const float4* p = (const float4*)(in + (size_t)g * 16);
    float4 A = p[0], B = p[1], C = p[2], D = p[3];
    A.x = rtf(A.x); A.y = rtf(A.y); A.z = rtf(A.z); A.w = rtf(A.w);
    B.x = rtf(B.x); B.y = rtf(B.y); B.z = rtf(B.z); B.w = rtf(B.w);
    C.x = rtf(C.x); C.y = rtf(C.y); C.z = rtf(C.z); C.w = rtf(C.w);
    D.x = rtf(D.x); D.y = rtf(D.y); D.z = rtf(D.z); D.w = rtf(D.w);
    float4* q = (float4*)(out + (size_t)g * 16);
    q[0] = make_float4(A.x, B.x, C.x, D.x);
    q[1] = make_float4(A.y, B.y, C.y, D.y);
    q[2] = make_float4(A.z, B.z, C.z, D.z);
    q[3] = make_float4(A.w, B.w, C.w, D.w);
}

// three weight matrices in one launch (grid.z selects source)
__global__ void round_perm_tf32_w3(const float* __restrict__ w0, const float* __restrict__ w1,
                                   const float* __restrict__ w2, float* __restrict__ out, int n16) {
    int g = blockIdx.x * blockDim.x + threadIdx.x;
    if (g >= n16) return;
    const float* in = (blockIdx.z == 0) ? w0 : (blockIdx.z == 1) ? w1 : w2;
    const float4* p = (const float4*)(in + (size_t)g * 16);
    float4 A = p[0], B = p[1], C = p[2], D = p[3];
    A.x = rtf(A.x); A.y = rtf(A.y); A.z = rtf(A.z); A.w = rtf(A.w);
    B.x = rtf(B.x); B.y = rtf(B.y); B.z = rtf(B.z); B.w = rtf(B.w);
    C.x = rtf(C.x); C.y = rtf(C.y); C.z = rtf(C.z); C.w = rtf(C.w);
    D.x = rtf(D.x); D.y = rtf(D.y); D.z = rtf(D.z); D.w = rtf(D.w);
    float4* q = (float4*)(out + (size_t)blockIdx.z * Dd * Dd + (size_t)g * 16);
    q[0] = make_float4(A.x, B.x, C.x, D.x);
    q[1] = make_float4(A.y, B.y, C.y, D.y);
    q[2] = make_float4(A.z, B.z, C.z, D.z);
    q[3] = make_float4(A.w, B.w, C.w, D.w);
}

// ---------------- TF32 GEMM (legacy mma.sync): C = A * B^T ----------------
// A, B tf32-rounded + 16-group-permuted in HBM. BK=32, chunk-swizzled smem
// (phys chunk = c ^ ((row&1)*4)), 3-stage cp.async ring, LDS.128 fragments:
// per 16-k: 12 LDS.128 + 32 HMMA (was 24 LDS.64 + 32 HMMA).
constexpr int BM = 128, BN = 128, BK = 32;
constexpr int NST = 3;
constexpr int STG_F = (BM + BN) * BK;            // 8192 floats per stage
constexpr int GEMM_SMEM = NST * STG_F * 4;       // 98304 bytes

__global__ void __launch_bounds__(256, 2) gemm_tf32(
    const float* __restrict__ A, const float* __restrict__ Bstk,
    float* __restrict__ Cstk, int roundMask)
{
    extern __shared__ float sm[];

    const int tid  = threadIdx.x;
    const int warp = tid >> 5, lane = tid & 31;
    const int wm = warp >> 1, wn = warp & 1;
    const int qr = lane >> 2, qc = lane & 3;
    const int bM = blockIdx.y * BM, bN = blockIdx.x * BN;
    const int z  = blockIdx.z;

    const float* Bm = Bstk + (size_t)z * Dd * Dd;
    float*       C  = Cstk + (size_t)z * MR * Dd;
    const bool doRound = (roundMask >> z) & 1;

    const float* Ag = A  + (size_t)bM * Dd;
    const float* Bg = Bm + (size_t)bN * Dd;

    float acc[2][8][4];
#pragma unroll
    for (int i = 0; i < 2; i++)
#pragma unroll
        for (int j = 0; j < 8; j++)
#pragma unroll
            for (int e = 0; e < 4; e++) acc[i][j][e] = 0.f;

    const int nt = Dd / BK;   // 64

    auto loadTile = [&](int st, int k0) {
        float* sA = sm + st * STG_F;
        float* sB = sA + BM * BK;
#pragma unroll
        for (int i = 0; i < 4; i++) {
            int f = tid + 256 * i;        // 0..1023 16B-chunk slots
            int row = f >> 3;
            int c16 = f & 7;
            int scol = (c16 ^ ((row & 1) * 4)) * 4;
            cp16(&sA[row * BK + scol], Ag + (size_t)row * Dd + k0 + c16 * 4);
            cp16(&sB[row * BK + scol], Bg + (size_t)row * Dd + k0 + c16 * 4);
        }
        cp_commit();
    };

    // fragment column: chunk (kk16/4 + qc) ^ ((qr&1)*4), in floats; col1 = col0 ^ 16
    const int col0 = ((qc ^ ((qr & 1) * 4)) << 2);

    loadTile(0, 0);        // g0 : tile 0
    loadTile(1, BK);       // g1 : tile 1

    int s0 = 0, s1 = 1, s2 = 2;
    for (int kt = 0; kt < nt; ++kt) {
        cp_wait<1>();      // tile kt resident (only tile kt+1 may be pending)
        __syncthreads();   // all warps done with tile kt-1 (buffer s2)
        if (kt + 2 < nt) loadTile(s2, (kt + 2) * BK);
        else             cp_commit();

        const float* tA = sm + s0 * STG_F + (wm * 32) * BK;
        const float* tB = sm + s0 * STG_F + BM * BK + (wn * 64) * BK;
#pragma unroll
        for (int h16 = 0; h16 < 2; h16++) {      // two 16-k halves of BK=32
            const int off = h16 ? (col0 ^ 16) : col0;
            uint4 a00 = *(const uint4*)&tA[(qr)      * BK + off];
            uint4 a01 = *(const uint4*)&tA[(qr + 8)  * BK + off];
            uint4 a10 = *(const uint4*)&tA[(16 + qr) * BK + off];
            uint4 a11 = *(const uint4*)&tA[(24 + qr) * BK + off];
#pragma unroll
            for (int nf = 0; nf < 8; nf++) {
                uint4 bb = *(const uint4*)&tB[(nf * 8 + qr) * BK + off];
                mma8s(acc[0][nf], a00.x, a01.x, a00.y, a01.y, bb.x, bb.y);
                mma8s(acc[1][nf], a10.x, a11.x, a10.y, a11.y, bb.x, bb.y);
                mma8s(acc[0][nf], a00.z, a01.z, a00.w, a01.w, bb.z, bb.w);
                mma8s(acc[1][nf], a10.z, a11.z, a10.w, a11.w, bb.z, bb.w);
            }
        }
        int t = s0; s0 = s1; s1 = s2; s2 = t;
    }

    // epilogue
#pragma unroll
    for (int mf = 0; mf < 2; mf++) {
#pragma unroll
        for (int nf = 0; nf < 8; nf++) {
            int col = bN + wn * 64 + nf * 8 + 2 * qc;
            int r0  = bM + wm * 32 + mf * 16 + qr;
            float v0 = acc[mf][nf][0], v1 = acc[mf][nf][1];
            float v2 = acc[mf][nf][2], v3 = acc[mf][nf][3];
            if (doRound) { v0 = rtf(v0); v1 = rtf(v1); v2 = rtf(v2); v3 = rtf(v3); }
            *(float2*)&C[(size_t)r0 * Dd + col]       = make_float2(v0, v1);
            *(float2*)&C[(size_t)(r0 + 8) * Dd + col] = make_float2(v2, v3);
        }
    }
}

// ---------------- RoPE ----------------
__global__ void rope_table() {
    int idx = blockIdx.x * blockDim.x + threadIdx.x;   // t*64 + i
    if (idx >= Tt * 64) return;
    int t = idx >> 6;
    int i = idx & 63;
    double theta = exp(-(double)i * (9.210340371976184 / 64.0));
    double ang   = (double)t * theta;
    g_cosT[idx] = (float)cos(ang);
    g_sinT[idx] = (float)sin(ang);
}

// applies rope to Q and K in place; output tf32-rounded AND 8-group k-permuted
// (p(k)=2k | 2k-7) for the flash S-loop's LDS.64 fragments.
__global__ void rope_apply() {
    int idx = blockIdx.x * blockDim.x + threadIdx.x;   // over MR * (Dd/2)
    int pair = idx & 1023;       // Dd/2 = 1024
    int row  = idx >> 10;
    int t = row & (Tt - 1);
    int i = pair & 63;           // within head (DH/2 = 64)
    float c = g_cosT[t * 64 + i];
    float s = g_sinT[t * 64 + i];
    size_t off = (size_t)row * Dd + pair * 2;
    float* Q = g_QKV;
    float* K = g_QKV + (size_t)MR * Dd;
    float2 q = *(float2*)&Q[off];
    float2 k = *(float2*)&K[off];
    float q0 = c * q.x - s * q.y, q1 = s * q.x + c * q.y;
    float k0 = c * k.x - s * k.y, k1 = s * k.x + c * k.y;
    int d  = pair * 2;
    size_t gb = (size_t)row * Dd + (d & ~7);
    int l0 = d & 7;                 // even: 0,2,4,6
    int l1 = l0 + 1;                // odd : 1,3,5,7
    int p0 = (l0 < 4) ? 2 * l0 : 2 * l0 - 7;
    int p1 = (l1 < 4) ? 2 * l1 : 2 * l1 - 7;
    Q[gb + p0] = rtf(q0);  Q[gb + p1] = rtf(q1);
    K[gb + p0] = rtf(k0);  K[gb + p1] = rtf(k1);
}

// ---------------- Flash attention (causal), legacy TF32 mma ----------------
// Q/K tf32-rounded + 8-group-permuted -> S-loop uses LDS.64 fragments.
// K double-buffered, V single-buffered, LPT scheduling.
// Epilogue writes g_AO with the 16-group permutation (consumed by final GEMM).
constexpr int TQ = 128, TS = 64;
constexpr int QST = DHd + 8;   // 136
constexpr int PST = TS + 4;    // 68
constexpr int FLASH_SMEM = (TQ * QST + 2 * TS * QST + TS * QST + 8 * 16 * PST) * 4;

__global__ void __launch_bounds__(256) flash_attn()
{
    extern __shared__ float sm[];
    float* sQ  = sm;                       // [128][136]
    float* sK0 = sQ  + TQ * QST;           // [64][136]
    float* sK1 = sK0 + TS * QST;           // [64][136]
    float* sV  = sK1 + TS * QST;           // [64][136]
    float* sP  = sV  + TS * QST;           // [8][16][68]

    const int qb = (gridDim.x - 1) - blockIdx.x;   // LPT: heavy blocks first
    const int bh = blockIdx.y;                     // 0..31
    const int b = bh >> 4, h = bh & 15;
    const int tid = threadIdx.x, warp = tid >> 5, lane = tid & 31;
    const int qr = lane >> 2, qc = lane & 3;

    const float* Qm = g_QKV;
    const float* Km = g_QKV + (size_t)MR * Dd;
    const float* Vm = g_QKV + (size_t)2 * MR * Dd;

    const size_t base = ((size_t)b * Tt) * Dd + (size_t)h * DHd;
    const float* Qg = Qm + base + (size_t)qb * TQ * Dd;

    // group c0: Q tile (128 x 128 floats)
#pragma unroll
    for (int i = 0; i < 16; i++) {
        int f = tid + 256 * i;
        int row = f >> 5;
        int col = (f & 31) * 4;
        cp16(&sQ[row * QST + col], Qg + (size_t)row * Dd + col);
    }
    cp_commit();

    const int kbmax = 2 * qb + 1;

    // group c1: K[0]
    {
        const float* Kg = Km + base;
#pragma unroll
        for (int i = 0; i < 8; i++) {
            int f = tid + 256 * i;
            int row = f >> 5;
            int col = (f & 31) * 4;
            cp16(&sK0[row * QST + col], Kg + (size_t)row * Dd + col);
        }
        cp_commit();
    }

    float o[16][4];
#pragma unroll
    for (int nf = 0; nf < 16; nf++)
#pragma unroll
        for (int e = 0; e < 4; e++) o[nf][e] = 0.f;
    float mrow[2] = { -1e30f, -1e30f };
    float lrow[2] = { 0.f, 0.f };

    for (int kb = 0; kb <= kbmax; ++kb) {
        float* curK = (kb & 1) ? sK1 : sK0;
        float* nxtK = (kb & 1) ? sK0 : sK1;

        {   // issue V[kb] -> group c_{2kb+2}
            const float* Vg = Vm + base + (size_t)kb * TS * Dd;
#pragma unroll
            for (int i = 0; i < 8; i++) {
                int f = tid + 256 * i;
                int row = f >> 5;
                int col = (f & 31) * 4;
                cp16(&sV[row * QST + col], Vg + (size_t)row * Dd + col);
            }
            cp_commit();
        }
        if (kb < kbmax) {   // issue K[kb+1] -> group c_{2kb+3}
            const float* Kg = Km + base + (size_t)(kb + 1) * TS * Dd;
#pragma unroll
            for (int i = 0; i < 8; i++) {
                int f = tid + 256 * i;
                int row = f >> 5;
                int col = (f & 31) * 4;
                cp16(&nxtK[row * QST + col], Kg + (size_t)row * Dd + col);
            }
        }
        cp_commit();        // empty group when kb == kbmax keeps numbering fixed

        cp_wait<2>();       // K[kb] ready; <=2 pending (V[kb], K[kb+1])
        __syncthreads();

        // ---- S = Q K^T (8-group-permuted operands -> LDS.64 fragments) ----
        float s[8][4];
#pragma unroll
        for (int nf = 0; nf < 8; nf++)
#pragma unroll
            for (int e = 0; e < 4; e++) s[nf][e] = 0.f;
        const float* tQ = sQ + (warp * 16) * QST;
#pragma unroll
        for (int kk = 0; kk < DHd; kk += 8) {
            uint32_t af[4];
            uint2 a0 = *(const uint2*)(tQ + qr * QST + kk + 2 * qc);
            uint2 a1 = *(const uint2*)(tQ + (qr + 8) * QST + kk + 2 * qc);
            af[0] = a0.x; af[1] = a1.x;
            af[2] = a0.y; af[3] = a1.y;
#pragma unroll
            for (int nf = 0; nf < 8; nf++) {
                uint2 bb = *(const uint2*)(curK + (nf * 8 + qr) * QST + kk + 2 * qc);
                mma8(s[nf], af, bb.x, bb.y);
            }
        }

        const float scale = 0.08838834764831845f;   // 1/sqrt(128)
        if (kb >= 2 * qb) {
            int rg0 = qb * TQ + warp * 16 + qr;
#pragma unroll
            for (int nf = 0; nf < 8; nf++)
#pragma unroll
                for (int e = 0; e < 4; e++) {
                    int r = rg0 + ((e >> 1) << 3);
                    int c = kb * TS + nf * 8 + 2 * qc + (e & 1);
                    s[nf][e] = (c > r) ? -1e30f : s[nf][e] * scale;
                }
        } else {
#pragma unroll
            for (int nf = 0; nf < 8; nf++)
#pragma unroll
                for (int e = 0; e < 4; e++) s[nf][e] *= scale;
        }

        // ---- online softmax ----
        float mx0 = -1e30f, mx1 = -1e30f;
#pragma unroll
        for (int nf = 0; nf < 8; nf++) {
            mx0 = fmaxf(mx0, fmaxf(s[nf][0], s[nf][1]));
            mx1 = fmaxf(mx1, fmaxf(s[nf][2], s[nf][3]));
        }
#pragma unroll
        for (int off = 1; off < 4; off <<= 1) {
            mx0 = fmaxf(mx0, __shfl_xor_sync(0xffffffffu, mx0, off));
            mx1 = fmaxf(mx1, __shfl_xor_sync(0xffffffffu, mx1, off));
        }
        float mn0 = fmaxf(mrow[0], mx0), mn1 = fmaxf(mrow[1], mx1);
        float al0 = __expf(mrow[0] - mn0), al1 = __expf(mrow[1] - mn1);
        mrow[0] = mn0; mrow[1] = mn1;
        float rs0 = 0.f, rs1 = 0.f;
#pragma unroll
        for (int nf = 0; nf < 8; nf++) {
            s[nf][0] = __expf(s[nf][0] - mn0);
            s[nf][1] = __expf(s[nf][1] - mn0);
            s[nf][2] = __expf(s[nf][2] - mn1);
            s[nf][3] = __expf(s[nf][3] - mn1);
            rs0 += s[nf][0] + s[nf][1];
            rs1 += s[nf][2] + s[nf][3];
        }
#pragma unroll
        for (int off = 1; off < 4; off <<= 1) {
            rs0 += __shfl_xor_sync(0xffffffffu, rs0, off);
            rs1 += __shfl_xor_sync(0xffffffffu, rs1, off);
        }
        lrow[0] = lrow[0] * al0 + rs0;
        lrow[1] = lrow[1] * al1 + rs1;
#pragma unroll
        for (int nf = 0; nf < 16; nf++) {
            o[nf][0] *= al0; o[nf][1] *= al0;
            o[nf][2] *= al1; o[nf][3] *= al1;
        }

        // ---- stage P ----
        float* wP = sP + warp * 16 * PST;
#pragma unroll
        for (int nf = 0; nf < 8; nf++) {
            int c = nf * 8 + 2 * qc;
            wP[qr * PST + c]           = s[nf][0];
            wP[qr * PST + c + 1]       = s[nf][1];
            wP[(qr + 8) * PST + c]     = s[nf][2];
            wP[(qr + 8) * PST + c + 1] = s[nf][3];
        }
        __syncwarp();

        cp_wait<1>();       // V[kb] ready; <=1 pending (K[kb+1])
        __syncthreads();    // cross-warp V visibility

        // ---- O += P V ----
#pragma unroll
        for (int kk = 0; kk < TS; kk += 8) {
            uint32_t af[4];
            const float* p = wP + qr * PST + kk + qc;
            af[0] = f2tf(p[0]);
            af[1] = f2tf(p[8 * PST]);
            af[2] = f2tf(p[4]);
            af[3] = f2tf(p[8 * PST + 4]);
#pragma unroll
            for (int nf = 0; nf < 16; nf++) {
                const uint32_t* pv = (const uint32_t*)(sV + (kk + qc) * QST + nf * 8 + qr);
                mma8(o[nf], af, pv[0], pv[4 * QST]);
            }
        }
        __syncthreads();    // V buffer + next-K buffer free for next iteration
    }

    // ---- epilogue: O /= l, tf32-round, 16-group permute, write to g_AO ----
    float inv0 = 1.f / lrow[0], inv1 = 1.f / lrow[1];
    float* Og = g_AO + ((size_t)b * Tt) * Dd + (size_t)h * DHd
              + ((size_t)qb * TQ + warp * 16) * Dd;
#pragma unroll
    for (int nf = 0; nf < 16; nf++) {
        int cA = nf * 8 + 2 * qc;
        int cB = cA + 1;
        int pA = (cA & ~15) + 4 * (cA & 3) + ((cA & 15) >> 2);
        int pB = (cB & ~15) + 4 * (cB & 3) + ((cB & 15) >> 2);
        Og[(size_t)qr * Dd + pA]       = rtf(o[nf][0] * inv0);
        Og[(size_t)qr * Dd + pB]       = rtf(o[nf][1] * inv0);
        Og[(size_t)(qr + 8) * Dd + pA] = rtf(o[nf][2] * inv1);
        Og[(size_t)(qr + 8) * Dd + pB] = rtf(o[nf][3] * inv1);
    }
}

// ---------------- launch ----------------
extern "C" void kernel_launch(void* const* d_in, const int* in_sizes, int n_in,
                              void* d_out, int out_size)
{
    const float* X  = (const float*)d_in[0];
    const float* Wq = (const float*)d_in[1];
    const float* Wk = (const float*)d_in[2];
    const float* Wv = (const float*)d_in[3];
    const float* Wo = (const float*)d_in[4];
    float* out = (float*)d_out;

    void *pQKV, *pA, *pXr, *pWr;
    cudaGetSymbolAddress(&pQKV, g_QKV);
    cudaGetSymbolAddress(&pA,   g_AO);
    cudaGetSymbolAddress(&pXr,  g_Xr);
    cudaGetSymbolAddress(&pWr,  g_Wr);

    cudaFuncSetAttribute(gemm_tf32,  cudaFuncAttributeMaxDynamicSharedMemorySize, GEMM_SMEM);
    cudaFuncSetAttribute(flash_attn, cudaFuncAttributeMaxDynamicSharedMemorySize, FLASH_SMEM);

    const int nX16 = (MR * Dd) / 16;
    const int nW16 = (Dd * Dd) / 16;
    float* Wr = (float*)pWr;

    rope_table<<<(Tt * 64) / 256, 256>>>();
    round_perm_tf32<<<(nX16 + 255) / 256, 256>>>(X, (float*)pXr, nX16);
    round_perm_tf32_w3<<<dim3((nW16 + 255) / 256, 1, 3), 256>>>(Wq, Wk, Wv, Wr, nW16);

    gemm_tf32<<<dim3(Dd / BN, MR / BM, 3), 256, GEMM_SMEM>>>(
        (const float*)pXr, Wr, (float*)pQKV, /*roundMask=*/0b100);

    rope_apply<<<(MR * 1024) / 256, 256>>>();
    flash_attn<<<dim3(Tt / TQ, Bb * Hh), 256, FLASH_SMEM>>>();

    round_perm_tf32<<<(nW16 + 255) / 256, 256>>>(Wo, Wr, nW16);
    gemm_tf32<<<dim3(Dd / BN, MR / BM, 1), 256, GEMM_SMEM>>>(
        (const float*)pA, Wr, out, /*roundMask=*/0);
}

// round 15
// speedup vs baseline: 1.0078x; 1.0078x over previous
#include <cuda_runtime.h>
#include <cstdint>
#include <math.h>

// Problem constants
#define Bb  2
#define Tt  2048
#define Dd  2048
#define Hh  16
#define DHd 128
#define MR  4096      // Bb*Tt rows

// ---------------- scratch (static device globals; no allocation) ----------------
// QKV stacked: Q at 0, K at +MR*Dd, V at +2*MR*Dd
__device__ float g_QKV[(size_t)3 * MR * Dd];
__device__ float g_AO [(size_t)MR * Dd];        // k-permuted + tf32-rounded attention out
__device__ float g_Xr [(size_t)MR * Dd];        // tf32-rounded + k-permuted X
__device__ float g_Wr [(size_t)3 * Dd * Dd];    // tf32-rounded + k-permuted weights (stacked)
__device__ float g_cosT[Tt * (DHd / 2)];
__device__ float g_sinT[Tt * (DHd / 2)];

// ---------------- helpers ----------------
__device__ __forceinline__ uint32_t f2tf(float x) {
    uint32_t r;
    asm("cvt.rna.tf32.f32 %0, %1;" : "=r"(r) : "f"(x));
    return r;
}
__device__ __forceinline__ float rtf(float x) { return __uint_as_float(f2tf(x)); }

__device__ __forceinline__ void mma8(float c[4], const uint32_t a[4], uint32_t b0, uint32_t b1) {
    asm volatile(
        "mma.sync.aligned.m16n8k8.row.col.f32.tf32.tf32.f32 "
        "{%0,%1,%2,%3}, {%4,%5,%6,%7}, {%8,%9}, {%0,%1,%2,%3};\n"
        : "+f"(c[0]), "+f"(c[1]), "+f"(c[2]), "+f"(c[3])
        : "r"(a[0]), "r"(a[1]), "r"(a[2]), "r"(a[3]), "r"(b0), "r"(b1));
}

__device__ __forceinline__ void cp16(float* s, const float* g) {
    uint32_t sa = (uint32_t)__cvta_generic_to_shared(s);
    asm volatile("cp.async.cg.shared.global [%0], [%1], 16;\n" :: "r"(sa), "l"(g));
}
__device__ __forceinline__ void cp_commit() { asm volatile("cp.async.commit_group;\n"); }
template <int N>
__device__ __forceinline__ void cp_wait() { asm volatile("cp.async.wait_group %0;\n" :: "n"(N)); }

// ---------------- tf32 round + k-permute: within each 8-group, out[p(k)]=in[k],
// p(k) = 2k (k<4), 2k-7 (k>=4) -> (k, k+4) land adjacent at (2k, 2k+1).
__global__ void round_perm_tf32(const float* __restrict__ in, float* __restrict__ out, int n8) {
    int g = blockIdx.x * blockDim.x + threadIdx.x;
    if (g >= n8) return;
    const float4* p = (const float4*)(in + (size_t)g * 8);
    float4 lo = p[0], hi = p[1];
    lo.x = rtf(lo.x); lo.y = rtf(lo.y); lo.z = rtf(lo.z); lo.w = rtf(lo.w);
    hi.x = rtf(hi.x); hi.y = rtf(hi.y); hi.z = rtf(hi.z); hi.w = rtf(hi.w);
    float4* q = (float4*)(out + (size_t)g * 8);
    q[0] = make_float4(lo.x, hi.x, lo.y, hi.y);   // positions 0..3  <- k = 0,4,1,5
    q[1] = make_float4(lo.z, hi.z, lo.w, hi.w);   // positions 4..7  <- k = 2,6,3,7
}

// three weight matrices in one launch (grid.z selects source)
__global__ void round_perm_tf32_w3(const float* __restrict__ w0, const float* __restrict__ w1,
                                   const float* __restrict__ w2, float* __restrict__ out, int n8) {
    int g = blockIdx.x * blockDim.x + threadIdx.x;
    if (g >= n8) return;
    const float* in = (blockIdx.z == 0) ? w0 : (blockIdx.z == 1) ? w1 : w2;
    const float4* p = (const float4*)(in + (size_t)g * 8);
    float4 lo = p[0], hi = p[1];
    lo.x = rtf(lo.x); lo.y = rtf(lo.y); lo.z = rtf(lo.z); lo.w = rtf(lo.w);
    hi.x = rtf(hi.x); hi.y = rtf(hi.y); hi.z = rtf(hi.z); hi.w = rtf(hi.w);
    float4* q = (float4*)(out + (size_t)blockIdx.z * Dd * Dd + (size_t)g * 8);
    q[0] = make_float4(lo.x, hi.x, lo.y, hi.y);
    q[1] = make_float4(lo.z, hi.z, lo.w, hi.w);
}

// ---------------- TF32 GEMM (legacy mma.sync): C = A * B^T ----------------
// A, B tf32-rounded + k-permuted in HBM. BK=32, XOR-swizzled smem (no padding),
// 3-stage cp.async ring (96KB -> 2 CTAs/SM), ONE __syncthreads per K-tile.
// ropeMask bit z: apply RoPE in epilogue (rows are tokens, cols are head dims),
// writing tf32-rounded + 8-group-permuted values (replaces the rope_apply pass).
constexpr int BM = 128, BN = 128, BK = 32;
constexpr int NST = 3;
constexpr int STG_F = (BM + BN) * BK;            // 8192 floats per stage
constexpr int GEMM_SMEM = NST * STG_F * 4;       // 98304 bytes

__global__ void __launch_bounds__(256, 2) gemm_tf32(
    const float* __restrict__ A, const float* __restrict__ Bstk,
    float* __restrict__ Cstk, int roundMask, int ropeMask)
{
    extern __shared__ float sm[];

    const int tid  = threadIdx.x;
    const int warp = tid >> 5, lane = tid & 31;
    const int wm = warp >> 1, wn = warp & 1;
    const int qr = lane >> 2, qc = lane & 3;
    const int bM = blockIdx.y * BM, bN = blockIdx.x * BN;
    const int z  = blockIdx.z;

    const float* Bm = Bstk + (size_t)z * Dd * Dd;
    float*       C  = Cstk + (size_t)z * MR * Dd;
    const bool doRound = (roundMask >> z) & 1;
    const bool doRope  = (ropeMask  >> z) & 1;

    const float* Ag = A  + (size_t)bM * Dd;
    const float* Bg = Bm + (size_t)bN * Dd;

    float acc[2][8][4];
#pragma unroll
    for (int i = 0; i < 2; i++)
#pragma unroll
        for (int j = 0; j < 8; j++)
#pragma unroll
            for (int e = 0; e < 4; e++) acc[i][j][e] = 0.f;

    const int nt = Dd / BK;   // 64

    auto loadTile = [&](int st, int k0) {
        float* sA = sm + st * STG_F;
        float* sB = sA + BM * BK;
#pragma unroll
        for (int i = 0; i < 4; i++) {
            int f = tid + 256 * i;        // 0..1023 16B-chunk slots
            int row = f >> 3;
            int c16 = f & 7;
            int scol = (c16 * 4) ^ ((row & 3) * 8);
            cp16(&sA[row * BK + scol], Ag + (size_t)row * Dd + k0 + c16 * 4);
            cp16(&sB[row * BK + scol], Bg + (size_t)row * Dd + k0 + c16 * 4);
        }
        cp_commit();
    };

    const int xr = (qr & 3) * 8;   // per-thread swizzle XOR

    loadTile(0, 0);        // g0 : tile 0
    loadTile(1, BK);       // g1 : tile 1

    int s0 = 0, s1 = 1, s2 = 2;
    for (int kt = 0; kt < nt; ++kt) {
        cp_wait<1>();      // tile kt resident (only tile kt+1 may be pending)
        __syncthreads();   // all warps done with tile kt-1 (buffer s2)
        if (kt + 2 < nt) loadTile(s2, (kt + 2) * BK);
        else             cp_commit();

        const float* tA = sm + s0 * STG_F + (wm * 32) * BK;
        const float* tB = sm + s0 * STG_F + BM * BK + (wn * 64) * BK;
#pragma unroll
        for (int kk = 0; kk < BK; kk += 8) {
            const int off = (kk ^ xr) + 2 * qc;
            uint32_t af[2][4];
#pragma unroll
            for (int mf = 0; mf < 2; mf++) {
                uint2 a0 = *(const uint2*)&tA[(mf * 16 + qr) * BK + off];
                uint2 a1 = *(const uint2*)&tA[(mf * 16 + qr + 8) * BK + off];
                af[mf][0] = a0.x; af[mf][1] = a1.x;
                af[mf][2] = a0.y; af[mf][3] = a1.y;
            }
#pragma unroll
            for (int nf = 0; nf < 8; nf++) {
                uint2 bb = *(const uint2*)&tB[(nf * 8 + qr) * BK + off];
                mma8(acc[0][nf], af[0], bb.x, bb.y);
                mma8(acc[1][nf], af[1], bb.x, bb.y);
            }
        }
        int t = s0; s0 = s1; s1 = s2; s2 = t;
    }

    // epilogue
#pragma unroll
    for (int mf = 0; mf < 2; mf++) {
#pragma unroll
        for (int nf = 0; nf < 8; nf++) {
            int col = bN + wn * 64 + nf * 8 + 2 * qc;   // even
            int r0  = bM + wm * 32 + mf * 16 + qr;
            float v0 = acc[mf][nf][0], v1 = acc[mf][nf][1];
            float v2 = acc[mf][nf][2], v3 = acc[mf][nf][3];
            if (doRope) {
                // rope pair (col, col+1); i = head-dim pair index
                int i  = (col & (DHd - 1)) >> 1;
                int t0 = r0 & (Tt - 1);
                int t1 = (r0 + 8) & (Tt - 1);
                float c0 = g_cosT[t0 * 64 + i], sn0 = g_sinT[t0 * 64 + i];
                float c1 = g_cosT[t1 * 64 + i], sn1 = g_sinT[t1 * 64 + i];
                float nv0 = c0 * v0 - sn0 * v1, nv1 = sn0 * v0 + c0 * v1;
                float nv2 = c1 * v2 - sn1 * v3, nv3 = sn1 * v2 + c1 * v3;
                // 8-group permuted positions for l0 = col&7 (even) and l0+1
                int l0 = col & 7, l1 = l0 + 1;
                int p0 = (l0 < 4) ? 2 * l0 : 2 * l0 - 7;
                int p1 = (l1 < 4) ? 2 * l1 : 2 * l1 - 7;
                size_t gb0 = (size_t)r0 * Dd + (col & ~7);
                size_t gb1 = (size_t)(r0 + 8) * Dd + (col & ~7);
                C[gb0 + p0] = rtf(nv0);  C[gb0 + p1] = rtf(nv1);
                C[gb1 + p0] = rtf(nv2);  C[gb1 + p1] = rtf(nv3);
            } else {
                if (doRound) { v0 = rtf(v0); v1 = rtf(v1); v2 = rtf(v2); v3 = rtf(v3); }
                *(float2*)&C[(size_t)r0 * Dd + col]       = make_float2(v0, v1);
                *(float2*)&C[(size_t)(r0 + 8) * Dd + col] = make_float2(v2, v3);
            }
        }
    }
}

// ---------------- RoPE table ----------------
__global__ void rope_table() {
    int idx = blockIdx.x * blockDim.x + threadIdx.x;   // t*64 + i
    if (idx >= Tt * 64) return;
    int t = idx >> 6;
    int i = idx & 63;
    double theta = exp(-(double)i * (9.210340371976184 / 64.0));
    double ang   = (double)t * theta;
    g_cosT[idx] = (float)cos(ang);
    g_sinT[idx] = (float)sin(ang);
}

// ---------------- Flash attention (causal), legacy TF32 mma ----------------
// Q/K in HBM are tf32-rounded AND k-permuted -> S-loop uses LDS.64 frag loads.
// K double-buffered, V single-buffered, LPT scheduling.
constexpr int TQ = 128, TS = 64;
constexpr int QST = DHd + 8;   // 136: stride mod 32 = 8 -> uint2 frag loads conflict-free
constexpr int PST = TS + 4;    // 68
constexpr int FLASH_SMEM = (TQ * QST + 2 * TS * QST + TS * QST + 8 * 16 * PST) * 4;

__global__ void __launch_bounds__(256) flash_attn()
{
    extern __shared__ float sm[];
    float* sQ  = sm;                       // [128][136]
    float* sK0 = sQ  + TQ * QST;           // [64][136]
    float* sK1 = sK0 + TS * QST;           // [64][136]
    float* sV  = sK1 + TS * QST;           // [64][136]
    float* sP  = sV  + TS * QST;           // [8][16][68]

    const int qb = (gridDim.x - 1) - blockIdx.x;   // LPT: heavy blocks first
    const int bh = blockIdx.y;                     // 0..31
    const int b = bh >> 4, h = bh & 15;
    const int tid = threadIdx.x, warp = tid >> 5, lane = tid & 31;
    const int qr = lane >> 2, qc = lane & 3;

    const float* Qm = g_QKV;
    const float* Km = g_QKV + (size_t)MR * Dd;
    const float* Vm = g_QKV + (size_t)2 * MR * Dd;

    const size_t base = ((size_t)b * Tt) * Dd + (size_t)h * DHd;
    const float* Qg = Qm + base + (size_t)qb * TQ * Dd;

    // group c0: Q tile (128 x 128 floats)
#pragma unroll
    for (int i = 0; i < 16; i++) {
        int f = tid + 256 * i;
        int row = f >> 5;
        int col = (f & 31) * 4;
        cp16(&sQ[row * QST + col], Qg + (size_t)row * Dd + col);
    }
    cp_commit();

    const int kbmax = 2 * qb + 1;

    // group c1: K[0]
    {
        const float* Kg = Km + base;
#pragma unroll
        for (int i = 0; i < 8; i++) {
            int f = tid + 256 * i;
            int row = f >> 5;
            int col = (f & 31) * 4;
            cp16(&sK0[row * QST + col], Kg + (size_t)row * Dd + col);
        }
        cp_commit();
    }

    float o[16][4];
#pragma unroll
    for (int nf = 0; nf < 16; nf++)
#pragma unroll
        for (int e = 0; e < 4; e++) o[nf][e] = 0.f;
    float mrow[2] = { -1e30f, -1e30f };
    float lrow[2] = { 0.f, 0.f };

    for (int kb = 0; kb <= kbmax; ++kb) {
        float* curK = (kb & 1) ? sK1 : sK0;
        float* nxtK = (kb & 1) ? sK0 : sK1;

        {   // issue V[kb] -> group c_{2kb+2}
            const float* Vg = Vm + base + (size_t)kb * TS * Dd;
#pragma unroll
            for (int i = 0; i < 8; i++) {
                int f = tid + 256 * i;
                int row = f >> 5;
                int col = (f & 31) * 4;
                cp16(&sV[row * QST + col], Vg + (size_t)row * Dd + col);
            }
            cp_commit();
        }
        if (kb < kbmax) {   // issue K[kb+1] -> group c_{2kb+3}
            const float* Kg = Km + base + (size_t)(kb + 1) * TS * Dd;
#pragma unroll
            for (int i = 0; i < 8; i++) {
                int f = tid + 256 * i;
                int row = f >> 5;
                int col = (f & 31) * 4;
                cp16(&nxtK[row * QST + col], Kg + (size_t)row * Dd + col);
            }
        }
        cp_commit();        // empty group when kb == kbmax keeps numbering fixed

        cp_wait<2>();       // K[kb] ready; <=2 pending (V[kb], K[kb+1])
        __syncthreads();

        // ---- S = Q K^T (k-permuted operands -> LDS.64 fragments) ----
        float s[8][4];
#pragma unroll
        for (int nf = 0; nf < 8; nf++)
#pragma unroll
            for (int e = 0; e < 4; e++) s[nf][e] = 0.f;
        const float* tQ = sQ + (warp * 16) * QST;
#pragma unroll
        for (int kk = 0; kk < DHd; kk += 8) {
            uint32_t af[4];
            uint2 a0 = *(const uint2*)(tQ + qr * QST + kk + 2 * qc);
            uint2 a1 = *(const uint2*)(tQ + (qr + 8) * QST + kk + 2 * qc);
            af[0] = a0.x; af[1] = a1.x;
            af[2] = a0.y; af[3] = a1.y;
#pragma unroll
            for (int nf = 0; nf < 8; nf++) {
                uint2 bb = *(const uint2*)(curK + (nf * 8 + qr) * QST + kk + 2 * qc);
                mma8(s[nf], af, bb.x, bb.y);
            }
        }

        const float scale = 0.08838834764831845f;   // 1/sqrt(128)
        if (kb >= 2 * qb) {
            int rg0 = qb * TQ + warp * 16 + qr;
#pragma unroll
            for (int nf = 0; nf < 8; nf++)
#pragma unroll
                for (int e = 0; e < 4; e++) {
                    int r = rg0 + ((e >> 1) << 3);
                    int c = kb * TS + nf * 8 + 2 * qc + (e & 1);
                    s[nf][e] = (c > r) ? -1e30f : s[nf][e] * scale;
                }
        } else {
#pragma unroll
            for (int nf = 0; nf < 8; nf++)
#pragma unroll
                for (int e = 0; e < 4; e++) s[nf][e] *= scale;
        }

        // ---- online softmax ----
        float mx0 = -1e30f, mx1 = -1e30f;
#pragma unroll
        for (int nf = 0; nf < 8; nf++) {
            mx0 = fmaxf(mx0, fmaxf(s[nf][0], s[nf][1]));
            mx1 = fmaxf(mx1, fmaxf(s[nf][2], s[nf][3]));
        }
#pragma unroll
        for (int off = 1; off < 4; off <<= 1) {
            mx0 = fmaxf(mx0, __shfl_xor_sync(0xffffffffu, mx0, off));
            mx1 = fmaxf(mx1, __shfl_xor_sync(0xffffffffu, mx1, off));
        }
        float mn0 = fmaxf(mrow[0], mx0), mn1 = fmaxf(mrow[1], mx1);
        float al0 = __expf(mrow[0] - mn0), al1 = __expf(mrow[1] - mn1);
        mrow[0] = mn0; mrow[1] = mn1;
        float rs0 = 0.f, rs1 = 0.f;
#pragma unroll
        for (int nf = 0; nf < 8; nf++) {
            s[nf][0] = __expf(s[nf][0] - mn0);
            s[nf][1] = __expf(s[nf][1] - mn0);
            s[nf][2] = __expf(s[nf][2] - mn1);
            s[nf][3] = __expf(s[nf][3] - mn1);
            rs0 += s[nf][0] + s[nf][1];
            rs1 += s[nf][2] + s[nf][3];
        }
#pragma unroll
        for (int off = 1; off < 4; off <<= 1) {
            rs0 += __shfl_xor_sync(0xffffffffu, rs0, off);
            rs1 += __shfl_xor_sync(0xffffffffu, rs1, off);
        }
        lrow[0] = lrow[0] * al0 + rs0;
        lrow[1] = lrow[1] * al1 + rs1;
#pragma unroll
        for (int nf = 0; nf < 16; nf++) {
            o[nf][0] *= al0; o[nf][1] *= al0;
            o[nf][2] *= al1; o[nf][3] *= al1;
        }

        // ---- stage P ----
        float* wP = sP + warp * 16 * PST;
#pragma unroll
        for (int nf = 0; nf < 8; nf++) {
            int c = nf * 8 + 2 * qc;
            wP[qr * PST + c]           = s[nf][0];
            wP[qr * PST + c + 1]       = s[nf][1];
            wP[(qr + 8) * PST + c]     = s[nf][2];
            wP[(qr + 8) * PST + c + 1] = s[nf][3];
        }
        __syncwarp();

        cp_wait<1>();       // V[kb] ready; <=1 pending (K[kb+1])
        __syncthreads();    // cross-warp V visibility

        // ---- O += P V ----
#pragma unroll
        for (int kk = 0; kk < TS; kk += 8) {
            uint32_t af[4];
            const float* p = wP + qr * PST + kk + qc;
            af[0] = f2tf(p[0]);
            af[1] = f2tf(p[8 * PST]);
            af[2] = f2tf(p[4]);
            af[3] = f2tf(p[8 * PST + 4]);
#pragma unroll
            for (int nf = 0; nf < 16; nf++) {
                const uint32_t* pv = (const uint32_t*)(sV + (kk + qc) * QST + nf * 8 + qr);
                mma8(o[nf], af, pv[0], pv[4 * QST]);
            }
        }
        __syncthreads();    // V buffer + next-K buffer free for next iteration
    }

    // ---- epilogue: O /= l, tf32-round, k-permute, write to g_AO ----
    float inv0 = 1.f / lrow[0], inv1 = 1.f / lrow[1];
    float* Og = g_AO + ((size_t)b * Tt) * Dd + (size_t)h * DHd
              + ((size_t)qb * TQ + warp * 16) * Dd;
    const int p0 = (qc < 2) ? 4 * qc : 4 * qc - 7;
    const int p1 = (qc < 2) ? 4 * qc + 2 : 4 * qc - 5;
#pragma unroll
    for (int nf = 0; nf < 16; nf++) {
        int gb = nf * 8;
        Og[(size_t)qr * Dd + gb + p0]       = rtf(o[nf][0] * inv0);
        Og[(size_t)qr * Dd + gb + p1]       = rtf(o[nf][1] * inv0);
        Og[(size_t)(qr + 8) * Dd + gb + p0] = rtf(o[nf][2] * inv1);
        Og[(size_t)(qr + 8) * Dd + gb + p1] = rtf(o[nf][3] * inv1);
    }
}

// ---------------- launch ----------------
extern "C" void kernel_launch(void* const* d_in, const int* in_sizes, int n_in,
                              void* d_out, int out_size)
{
    const float* X  = (const float*)d_in[0];
    const float* Wq = (const float*)d_in[1];
    const float* Wk = (const float*)d_in[2];
    const float* Wv = (const float*)d_in[3];
    const float* Wo = (const float*)d_in[4];
    float* out = (float*)d_out;

    void *pQKV, *pA, *pXr, *pWr;
    cudaGetSymbolAddress(&pQKV, g_QKV);
    cudaGetSymbolAddress(&pA,   g_AO);
    cudaGetSymbolAddress(&pXr,  g_Xr);
    cudaGetSymbolAddress(&pWr,  g_Wr);

    cudaFuncSetAttribute(gemm_tf32,  cudaFuncAttributeMaxDynamicSharedMemorySize, GEMM_SMEM);
    cudaFuncSetAttribute(flash_attn, cudaFuncAttributeMaxDynamicSharedMemorySize, FLASH_SMEM);

    const int nX8 = (MR * Dd) / 8;
    const int nW8 = (Dd * Dd) / 8;
    float* Wr = (float*)pWr;

    rope_table<<<(Tt * 64) / 256, 256>>>();
    round_perm_tf32<<<(nX8 + 255) / 256, 256>>>(X, (float*)pXr, nX8);
    round_perm_tf32_w3<<<dim3((nW8 + 255) / 256, 1, 3), 256>>>(Wq, Wk, Wv, Wr, nW8);

    // fused QKV projection; rope applied in epilogue for Q (z=0) and K (z=1),
    // V (z=2) rounded to tf32. No separate rope pass.
    gemm_tf32<<<dim3(Dd / BN, MR / BM, 3), 256, GEMM_SMEM>>>(
        (const float*)pXr, Wr, (float*)pQKV, /*roundMask=*/0b100, /*ropeMask=*/0b011);

    flash_attn<<<dim3(Tt / TQ, Bb * Hh), 256, FLASH_SMEM>>>();

    round_perm_tf32<<<(nW8 + 255) / 256, 256>>>(Wo, Wr, nW8);
    gemm_tf32<<<dim3(Dd / BN, MR / BM, 1), 256, GEMM_SMEM>>>(
        (const float*)pA, Wr, out, /*roundMask=*/0, /*ropeMask=*/0);
}

// round 16
// speedup vs baseline: 1.0471x; 1.0390x over previous
#include <cuda_runtime.h>
#include <cstdint>
#include <math.h>

// Problem constants
#define Bb  2
#define Tt  2048
#define Dd  2048
#define Hh  16
#define DHd 128
#define MR  4096      // Bb*Tt rows

// ---------------- scratch (static device globals; no allocation) ----------------
// QKV stacked: Q at 0, K at +MR*Dd, V at +2*MR*Dd
__device__ float g_QKV[(size_t)3 * MR * Dd];
__device__ float g_AO [(size_t)MR * Dd];        // k-permuted + tf32-rounded attention out
__device__ float g_Xr [(size_t)MR * Dd];        // tf32-rounded + k-permuted X
__device__ float g_Wr [(size_t)4 * Dd * Dd];    // rounded+permuted weights: Wq,Wk,Wv,Wo
__device__ float g_cosT[Tt * (DHd / 2)];
__device__ float g_sinT[Tt * (DHd / 2)];

// ---------------- helpers ----------------
__device__ __forceinline__ uint32_t f2tf(float x) {
    uint32_t r;
    asm("cvt.rna.tf32.f32 %0, %1;" : "=r"(r) : "f"(x));
    return r;
}
__device__ __forceinline__ float rtf(float x) { return __uint_as_float(f2tf(x)); }

__device__ __forceinline__ void mma8(float c[4], const uint32_t a[4], uint32_t b0, uint32_t b1) {
    asm volatile(
        "mma.sync.aligned.m16n8k8.row.col.f32.tf32.tf32.f32 "
        "{%0,%1,%2,%3}, {%4,%5,%6,%7}, {%8,%9}, {%0,%1,%2,%3};\n"
        : "+f"(c[0]), "+f"(c[1]), "+f"(c[2]), "+f"(c[3])
        : "r"(a[0]), "r"(a[1]), "r"(a[2]), "r"(a[3]), "r"(b0), "r"(b1));
}

__device__ __forceinline__ void cp16(float* s, const float* g) {
    uint32_t sa = (uint32_t)__cvta_generic_to_shared(s);
    asm volatile("cp.async.cg.shared.global [%0], [%1], 16;\n" :: "r"(sa), "l"(g));
}
__device__ __forceinline__ void cp_commit() { asm volatile("cp.async.commit_group;\n"); }
template <int N>
__device__ __forceinline__ void cp_wait() { asm volatile("cp.async.wait_group %0;\n" :: "n"(N)); }

// ---------------- tf32 round + k-permute: within each 8-group, out[p(k)]=in[k],
// p(k) = 2k (k<4), 2k-7 (k>=4) -> (k, k+4) land adjacent at (2k, 2k+1).
__global__ void round_perm_tf32(const float* __restrict__ in, float* __restrict__ out, int n8) {
    int g = blockIdx.x * blockDim.x + threadIdx.x;
    if (g >= n8) return;
    const float4* p = (const float4*)(in + (size_t)g * 8);
    float4 lo = p[0], hi = p[1];
    lo.x = rtf(lo.x); lo.y = rtf(lo.y); lo.z = rtf(lo.z); lo.w = rtf(lo.w);
    hi.x = rtf(hi.x); hi.y = rtf(hi.y); hi.z = rtf(hi.z); hi.w = rtf(hi.w);
    float4* q = (float4*)(out + (size_t)g * 8);
    q[0] = make_float4(lo.x, hi.x, lo.y, hi.y);   // positions 0..3  <- k = 0,4,1,5
    q[1] = make_float4(lo.z, hi.z, lo.w, hi.w);   // positions 4..7  <- k = 2,6,3,7
}

// four weight matrices in one launch (grid.z selects source)
__global__ void round_perm_tf32_w4(const float* __restrict__ w0, const float* __restrict__ w1,
                                   const float* __restrict__ w2, const float* __restrict__ w3,
                                   float* __restrict__ out, int n8) {
    int g = blockIdx.x * blockDim.x + threadIdx.x;
    if (g >= n8) return;
    const float* in = (blockIdx.z == 0) ? w0 : (blockIdx.z == 1) ? w1
                    : (blockIdx.z == 2) ? w2 : w3;
    const float4* p = (const float4*)(in + (size_t)g * 8);
    float4 lo = p[0], hi = p[1];
    lo.x = rtf(lo.x); lo.y = rtf(lo.y); lo.z = rtf(lo.z); lo.w = rtf(lo.w);
    hi.x = rtf(hi.x); hi.y = rtf(hi.y); hi.z = rtf(hi.z); hi.w = rtf(hi.w);
    float4* q = (float4*)(out + (size_t)blockIdx.z * Dd * Dd + (size_t)g * 8);
    q[0] = make_float4(lo.x, hi.x, lo.y, hi.y);
    q[1] = make_float4(lo.z, hi.z, lo.w, hi.w);
}

// ---------------- TF32 GEMM (legacy mma.sync): C = A * B^T ----------------
// A, B tf32-rounded + k-permuted in HBM. BK=32, XOR-swizzled smem (no padding),
// 3-stage cp.async ring (96KB -> 2 CTAs/SM), ONE __syncthreads per K-tile.
constexpr int BM = 128, BN = 128, BK = 32;
constexpr int NST = 3;
constexpr int STG_F = (BM + BN) * BK;            // 8192 floats per stage
constexpr int GEMM_SMEM = NST * STG_F * 4;       // 98304 bytes

__global__ void __launch_bounds__(256, 2) gemm_tf32(
    const float* __restrict__ A, const float* __restrict__ Bstk,
    float* __restrict__ Cstk, int roundMask)
{
    extern __shared__ float sm[];

    const int tid  = threadIdx.x;
    const int warp = tid >> 5, lane = tid & 31;
    const int wm = warp >> 1, wn = warp & 1;
    const int qr = lane >> 2, qc = lane & 3;
    const int bM = blockIdx.y * BM, bN = blockIdx.x * BN;
    const int z  = blockIdx.z;

    const float* Bm = Bstk + (size_t)z * Dd * Dd;
    float*       C  = Cstk + (size_t)z * MR * Dd;
    const bool doRound = (roundMask >> z) & 1;

    const float* Ag = A  + (size_t)bM * Dd;
    const float* Bg = Bm + (size_t)bN * Dd;

    float acc[2][8][4];
#pragma unroll
    for (int i = 0; i < 2; i++)
#pragma unroll
        for (int j = 0; j < 8; j++)
#pragma unroll
            for (int e = 0; e < 4; e++) acc[i][j][e] = 0.f;

    const int nt = Dd / BK;   // 64

    auto loadTile = [&](int st, int k0) {
        float* sA = sm + st * STG_F;
        float* sB = sA + BM * BK;
#pragma unroll
        for (int i = 0; i < 4; i++) {
            int f = tid + 256 * i;        // 0..1023 16B-chunk slots
            int row = f >> 3;
            int c16 = f & 7;
            int scol = (c16 * 4) ^ ((row & 3) * 8);
            cp16(&sA[row * BK + scol], Ag + (size_t)row * Dd + k0 + c16 * 4);
            cp16(&sB[row * BK + scol], Bg + (size_t)row * Dd + k0 + c16 * 4);
        }
        cp_commit();
    };

    const int xr = (qr & 3) * 8;   // per-thread swizzle XOR

    loadTile(0, 0);        // g0 : tile 0
    loadTile(1, BK);       // g1 : tile 1

    int s0 = 0, s1 = 1, s2 = 2;
    for (int kt = 0; kt < nt; ++kt) {
        cp_wait<1>();      // tile kt resident (only tile kt+1 may be pending)
        __syncthreads();   // all warps done with tile kt-1 (buffer s2)
        if (kt + 2 < nt) loadTile(s2, (kt + 2) * BK);
        else             cp_commit();

        const float* tA = sm + s0 * STG_F + (wm * 32) * BK;
        const float* tB = sm + s0 * STG_F + BM * BK + (wn * 64) * BK;
#pragma unroll
        for (int kk = 0; kk < BK; kk += 8) {
            const int off = (kk ^ xr) + 2 * qc;
            uint32_t af[2][4];
#pragma unroll
            for (int mf = 0; mf < 2; mf++) {
                uint2 a0 = *(const uint2*)&tA[(mf * 16 + qr) * BK + off];
                uint2 a1 = *(const uint2*)&tA[(mf * 16 + qr + 8) * BK + off];
                af[mf][0] = a0.x; af[mf][1] = a1.x;
                af[mf][2] = a0.y; af[mf][3] = a1.y;
            }
#pragma unroll
            for (int nf = 0; nf < 8; nf++) {
                uint2 bb = *(const uint2*)&tB[(nf * 8 + qr) * BK + off];
                mma8(acc[0][nf], af[0], bb.x, bb.y);
                mma8(acc[1][nf], af[1], bb.x, bb.y);
            }
        }
        int t = s0; s0 = s1; s1 = s2; s2 = t;
    }

    // epilogue
#pragma unroll
    for (int mf = 0; mf < 2; mf++) {
#pragma unroll
        for (int nf = 0; nf < 8; nf++) {
            int col = bN + wn * 64 + nf * 8 + 2 * qc;
            int r0  = bM + wm * 32 + mf * 16 + qr;
            float v0 = acc[mf][nf][0], v1 = acc[mf][nf][1];
            float v2 = acc[mf][nf][2], v3 = acc[mf][nf][3];
            if (doRound) { v0 = rtf(v0); v1 = rtf(v1); v2 = rtf(v2); v3 = rtf(v3); }
            *(float2*)&C[(size_t)r0 * Dd + col]       = make_float2(v0, v1);
            *(float2*)&C[(size_t)(r0 + 8) * Dd + col] = make_float2(v2, v3);
        }
    }
}

// ---------------- RoPE ----------------
__global__ void rope_table() {
    int idx = blockIdx.x * blockDim.x + threadIdx.x;   // t*64 + i
    if (idx >= Tt * 64) return;
    int t = idx >> 6;
    int i = idx & 63;
    double theta = exp(-(double)i * (9.210340371976184 / 64.0));
    double ang   = (double)t * theta;
    g_cosT[idx] = (float)cos(ang);
    g_sinT[idx] = (float)sin(ang);
}

// applies rope to Q and K in place; output tf32-rounded AND k-permuted within
// each head-dim 8-group (p(k)=2k | 2k-7), so flash frag loads can use LDS.64.
__global__ void rope_apply() {
    int idx = blockIdx.x * blockDim.x + threadIdx.x;   // over MR * (Dd/2)
    int pair = idx & 1023;       // Dd/2 = 1024
    int row  = idx >> 10;
    int t = row & (Tt - 1);
    int i = pair & 63;           // within head (DH/2 = 64)
    float c = g_cosT[t * 64 + i];
    float s = g_sinT[t * 64 + i];
    size_t off = (size_t)row * Dd + pair * 2;
    float* Q = g_QKV;
    float* K = g_QKV + (size_t)MR * Dd;
    float2 q = *(float2*)&Q[off];
    float2 k = *(float2*)&K[off];
    float q0 = c * q.x - s * q.y, q1 = s * q.x + c * q.y;
    float k0 = c * k.x - s * k.y, k1 = s * k.x + c * k.y;
    int d  = pair * 2;
    size_t gb = (size_t)row * Dd + (d & ~7);
    int l0 = d & 7;                 // even: 0,2,4,6
    int l1 = l0 + 1;                // odd : 1,3,5,7
    int p0 = (l0 < 4) ? 2 * l0 : 2 * l0 - 7;
    int p1 = (l1 < 4) ? 2 * l1 : 2 * l1 - 7;
    Q[gb + p0] = rtf(q0);  Q[gb + p1] = rtf(q1);
    K[gb + p0] = rtf(k0);  K[gb + p1] = rtf(k1);
}

// ---------------- Flash attention (causal), legacy TF32 mma ----------------
// Q/K in HBM are tf32-rounded AND k-permuted -> S-loop uses LDS.64 frag loads.
// K double-buffered, V single-buffered, LPT scheduling.
constexpr int TQ = 128, TS = 64;
constexpr int QST = DHd + 8;   // 136: stride mod 32 = 8 -> uint2 frag loads conflict-free
constexpr int PST = TS + 4;    // 68
constexpr int FLASH_SMEM = (TQ * QST + 2 * TS * QST + TS * QST + 8 * 16 * PST) * 4;

__global__ void __launch_bounds__(256) flash_attn()
{
    extern __shared__ float sm[];
    float* sQ  = sm;                       // [128][136]
    float* sK0 = sQ  + TQ * QST;           // [64][136]
    float* sK1 = sK0 + TS * QST;           // [64][136]
    float* sV  = sK1 + TS * QST;           // [64][136]
    float* sP  = sV  + TS * QST;           // [8][16][68]

    const int qb = (gridDim.x - 1) - blockIdx.x;   // LPT: heavy blocks first
    const int bh = blockIdx.y;                     // 0..31
    const int b = bh >> 4, h = bh & 15;
    const int tid = threadIdx.x, warp = tid >> 5, lane = tid & 31;
    const int qr = lane >> 2, qc = lane & 3;

    const float* Qm = g_QKV;
    const float* Km = g_QKV + (size_t)MR * Dd;
    const float* Vm = g_QKV + (size_t)2 * MR * Dd;

    const size_t base = ((size_t)b * Tt) * Dd + (size_t)h * DHd;
    const float* Qg = Qm + base + (size_t)qb * TQ * Dd;

    // group c0: Q tile (128 x 128 floats)
#pragma unroll
    for (int i = 0; i < 16; i++) {
        int f = tid + 256 * i;
        int row = f >> 5;
        int col = (f & 31) * 4;
        cp16(&sQ[row * QST + col], Qg + (size_t)row * Dd + col);
    }
    cp_commit();

    const int kbmax = 2 * qb + 1;

    // group c1: K[0]
    {
        const float* Kg = Km + base;
#pragma unroll
        for (int i = 0; i < 8; i++) {
            int f = tid + 256 * i;
            int row = f >> 5;
            int col = (f & 31) * 4;
            cp16(&sK0[row * QST + col], Kg + (size_t)row * Dd + col);
        }
        cp_commit();
    }

    float o[16][4];
#pragma unroll
    for (int nf = 0; nf < 16; nf++)
#pragma unroll
        for (int e = 0; e < 4; e++) o[nf][e] = 0.f;
    float mrow[2] = { -1e30f, -1e30f };
    float lrow[2] = { 0.f, 0.f };

    for (int kb = 0; kb <= kbmax; ++kb) {
        float* curK = (kb & 1) ? sK1 : sK0;
        float* nxtK = (kb & 1) ? sK0 : sK1;

        {   // issue V[kb] -> group c_{2kb+2}
            const float* Vg = Vm + base + (size_t)kb * TS * Dd;
#pragma unroll
            for (int i = 0; i < 8; i++) {
                int f = tid + 256 * i;
                int row = f >> 5;
                int col = (f & 31) * 4;
                cp16(&sV[row * QST + col], Vg + (size_t)row * Dd + col);
            }
            cp_commit();
        }
        if (kb < kbmax) {   // issue K[kb+1] -> group c_{2kb+3}
            const float* Kg = Km + base + (size_t)(kb + 1) * TS * Dd;
#pragma unroll
            for (int i = 0; i < 8; i++) {
                int f = tid + 256 * i;
                int row = f >> 5;
                int col = (f & 31) * 4;
                cp16(&nxtK[row * QST + col], Kg + (size_t)row * Dd + col);
            }
        }
        cp_commit();        // empty group when kb == kbmax keeps numbering fixed

        cp_wait<2>();       // K[kb] ready; <=2 pending (V[kb], K[kb+1])
        __syncthreads();

        // ---- S = Q K^T (k-permuted operands -> LDS.64 fragments) ----
        float s[8][4];
#pragma unroll
        for (int nf = 0; nf < 8; nf++)
#pragma unroll
            for (int e = 0; e < 4; e++) s[nf][e] = 0.f;
        const float* tQ = sQ + (warp * 16) * QST;
#pragma unroll
        for (int kk = 0; kk < DHd; kk += 8) {
            uint32_t af[4];
            uint2 a0 = *(const uint2*)(tQ + qr * QST + kk + 2 * qc);
            uint2 a1 = *(const uint2*)(tQ + (qr + 8) * QST + kk + 2 * qc);
            af[0] = a0.x; af[1] = a1.x;
            af[2] = a0.y; af[3] = a1.y;
#pragma unroll
            for (int nf = 0; nf < 8; nf++) {
                uint2 bb = *(const uint2*)(curK + (nf * 8 + qr) * QST + kk + 2 * qc);
                mma8(s[nf], af, bb.x, bb.y);
            }
        }

        const float scale = 0.08838834764831845f;   // 1/sqrt(128)
        if (kb >= 2 * qb) {
            int rg0 = qb * TQ + warp * 16 + qr;
#pragma unroll
            for (int nf = 0; nf < 8; nf++)
#pragma unroll
                for (int e = 0; e < 4; e++) {
                    int r = rg0 + ((e >> 1) << 3);
                    int c = kb * TS + nf * 8 + 2 * qc + (e & 1);
                    s[nf][e] = (c > r) ? -1e30f : s[nf][e] * scale;
                }
        } else {
#pragma unroll
            for (int nf = 0; nf < 8; nf++)
#pragma unroll
                for (int e = 0; e < 4; e++) s[nf][e] *= scale;
        }

        // ---- online softmax ----
        float mx0 = -1e30f, mx1 = -1e30f;
#pragma unroll
        for (int nf = 0; nf < 8; nf++) {
            mx0 = fmaxf(mx0, fmaxf(s[nf][0], s[nf][1]));
            mx1 = fmaxf(mx1, fmaxf(s[nf][2], s[nf][3]));
        }
#pragma unroll
        for (int off = 1; off < 4; off <<= 1) {
            mx0 = fmaxf(mx0, __shfl_xor_sync(0xffffffffu, mx0, off));
            mx1 = fmaxf(mx1, __shfl_xor_sync(0xffffffffu, mx1, off));
        }
        float mn0 = fmaxf(mrow[0], mx0), mn1 = fmaxf(mrow[1], mx1);
        float al0 = __expf(mrow[0] - mn0), al1 = __expf(mrow[1] - mn1);
        mrow[0] = mn0; mrow[1] = mn1;
        float rs0 = 0.f, rs1 = 0.f;
#pragma unroll
        for (int nf = 0; nf < 8; nf++) {
            s[nf][0] = __expf(s[nf][0] - mn0);
            s[nf][1] = __expf(s[nf][1] - mn0);
            s[nf][2] = __expf(s[nf][2] - mn1);
            s[nf][3] = __expf(s[nf][3] - mn1);
            rs0 += s[nf][0] + s[nf][1];
            rs1 += s[nf][2] + s[nf][3];
        }
#pragma unroll
        for (int off = 1; off < 4; off <<= 1) {
            rs0 += __shfl_xor_sync(0xffffffffu, rs0, off);
            rs1 += __shfl_xor_sync(0xffffffffu, rs1, off);
        }
        lrow[0] = lrow[0] * al0 + rs0;
        lrow[1] = lrow[1] * al1 + rs1;
#pragma unroll
        for (int nf = 0; nf < 16; nf++) {
            o[nf][0] *= al0; o[nf][1] *= al0;
            o[nf][2] *= al1; o[nf][3] *= al1;
        }

        // ---- stage P ----
        float* wP = sP + warp * 16 * PST;
#pragma unroll
        for (int nf = 0; nf < 8; nf++) {
            int c = nf * 8 + 2 * qc;
            wP[qr * PST + c]           = s[nf][0];
            wP[qr * PST + c + 1]       = s[nf][1];
            wP[(qr + 8) * PST + c]     = s[nf][2];
            wP[(qr + 8) * PST + c + 1] = s[nf][3];
        }
        __syncwarp();

        cp_wait<1>();       // V[kb] ready; <=1 pending (K[kb+1])
        __syncthreads();    // cross-warp V visibility

        // ---- O += P V ----
#pragma unroll
        for (int kk = 0; kk < TS; kk += 8) {
            uint32_t af[4];
            const float* p = wP + qr * PST + kk + qc;
            af[0] = f2tf(p[0]);
            af[1] = f2tf(p[8 * PST]);
            af[2] = f2tf(p[4]);
            af[3] = f2tf(p[8 * PST + 4]);
#pragma unroll
            for (int nf = 0; nf < 16; nf++) {
                const uint32_t* pv = (const uint32_t*)(sV + (kk + qc) * QST + nf * 8 + qr);
                mma8(o[nf], af, pv[0], pv[4 * QST]);
            }
        }
        __syncthreads();    // V buffer + next-K buffer free for next iteration
    }

    // ---- epilogue: O /= l, tf32-round, k-permute, write to g_AO ----
    float inv0 = 1.f / lrow[0], inv1 = 1.f / lrow[1];
    float* Og = g_AO + ((size_t)b * Tt) * Dd + (size_t)h * DHd
              + ((size_t)qb * TQ + warp * 16) * Dd;
    const int p0 = (qc < 2) ? 4 * qc : 4 * qc - 7;
    const int p1 = (qc < 2) ? 4 * qc + 2 : 4 * qc - 5;
#pragma unroll
    for (int nf = 0; nf < 16; nf++) {
        int gb = nf * 8;
        Og[(size_t)qr * Dd + gb + p0]       = rtf(o[nf][0] * inv0);
        Og[(size_t)qr * Dd + gb + p1]       = rtf(o[nf][1] * inv0);
        Og[(size_t)(qr + 8) * Dd + gb + p0] = rtf(o[nf][2] * inv1);
        Og[(size_t)(qr + 8) * Dd + gb + p1] = rtf(o[nf][3] * inv1);
    }
}

// ---------------- launch ----------------
extern "C" void kernel_launch(void* const* d_in, const int* in_sizes, int n_in,
                              void* d_out, int out_size)
{
    const float* X  = (const float*)d_in[0];
    const float* Wq = (const float*)d_in[1];
    const float* Wk = (const float*)d_in[2];
    const float* Wv = (const float*)d_in[3];
    const float* Wo = (const float*)d_in[4];
    float* out = (float*)d_out;

    void *pQKV, *pA, *pXr, *pWr;
    cudaGetSymbolAddress(&pQKV, g_QKV);
    cudaGetSymbolAddress(&pA,   g_AO);
    cudaGetSymbolAddress(&pXr,  g_Xr);
    cudaGetSymbolAddress(&pWr,  g_Wr);

    cudaFuncSetAttribute(gemm_tf32,  cudaFuncAttributeMaxDynamicSharedMemorySize, GEMM_SMEM);
    cudaFuncSetAttribute(flash_attn, cudaFuncAttributeMaxDynamicSharedMemorySize, FLASH_SMEM);

    const int nX8 = (MR * Dd) / 8;
    const int nW8 = (Dd * Dd) / 8;
    float* Wr = (float*)pWr;

    rope_table<<<(Tt * 64) / 256, 256>>>();
    round_perm_tf32<<<(nX8 + 255) / 256, 256>>>(X, (float*)pXr, nX8);
    // all four weight matrices rounded+permuted in ONE launch (Wo -> slab 3)
    round_perm_tf32_w4<<<dim3((nW8 + 255) / 256, 1, 4), 256>>>(Wq, Wk, Wv, Wo, Wr, nW8);

    // fused Q,K,V projection: grid.z = 3; round V (z=2) output to tf32
    gemm_tf32<<<dim3(Dd / BN, MR / BM, 3), 256, GEMM_SMEM>>>(
        (const float*)pXr, Wr, (float*)pQKV, /*roundMask=*/0b100);

    rope_apply<<<(MR * 1024) / 256, 256>>>();
    flash_attn<<<dim3(Tt / TQ, Bb * Hh), 256, FLASH_SMEM>>>();

    // output projection: Wo already rounded in slab 3
    gemm_tf32<<<dim3(Dd / BN, MR / BM, 1), 256, GEMM_SMEM>>>(
        (const float*)pA, Wr + (size_t)3 * Dd * Dd, out, /*roundMask=*/0);
}